// round 13
// baseline (speedup 1.0000x reference)
#include <cuda_runtime.h>
#include <math.h>
#include <stdint.h>

#define NEL 32
#define NUP 16
#define NI  32
#define NL  16
#define NK  16
#define H1  128
#define H2  4
#define FLEN 392
#define GRID 128

// ---- device-global state (no allocation allowed) ----
__device__ float g_sh[2][NEL][H1];
__device__ float g_mean[NL][256];      // [layer][ up(128) | dn(128) ]
__device__ float g_rN[NEL][NI];
__device__ float g_phi[NK][2][16][16];
__device__ float g_det[NK][2];
__device__ unsigned g_bar[NL + 2];

// ---------------- R2's barrier, verbatim ----------------
__device__ __forceinline__ unsigned ld_acq(const unsigned* p) {
    unsigned v;
    asm volatile("ld.acquire.gpu.global.u32 %0, [%1];" : "=r"(v) : "l"(p) : "memory");
    return v;
}
__device__ __forceinline__ void red_rel_add1(unsigned* p) {
    asm volatile("red.release.gpu.global.add.u32 [%0], 1;" :: "l"(p) : "memory");
}
__device__ __forceinline__ void red_add_f32(float* p, float v) {
    asm volatile("red.relaxed.gpu.global.add.f32 [%0], %1;" :: "l"(p), "f"(v) : "memory");
}
__device__ __forceinline__ void bar_arrive(int idx) {
    __syncthreads();
    if (threadIdx.x == 0) red_rel_add1(&g_bar[idx]);
}
__device__ __forceinline__ void bar_wait(int idx, unsigned target) {
    if (threadIdx.x == 0) {
        while (ld_acq(&g_bar[idx]) < target) { }
    }
    __syncthreads();
}

// ---------------- cluster / DSMEM helpers ----------------
__device__ __forceinline__ void cluster_arrive() {
    asm volatile("barrier.cluster.arrive.aligned;" ::: "memory");
}
__device__ __forceinline__ void cluster_wait() {
    asm volatile("barrier.cluster.wait.aligned;" ::: "memory");
}
__device__ __forceinline__ uint32_t mapa_addr(uint32_t saddr, int rank) {
    uint32_t r;
    asm("mapa.shared::cluster.u32 %0, %1, %2;" : "=r"(r) : "r"(saddr), "r"(rank));
    return r;
}
__device__ __forceinline__ void st_dsm(uint32_t saddr, float v) {
    asm volatile("st.shared::cluster.f32 [%0], %1;" :: "r"(saddr), "f"(v) : "memory");
}

// ---------------------------------------------------------------------------
// Preprocess: sh^0 + rN + g_mean[0] + zero accumulators/counters (every replay)
// ---------------------------------------------------------------------------
__global__ void pre_kernel(const float* __restrict__ ep,
                           const float* __restrict__ nuc) {
    int t = threadIdx.x;
    if (t < NL + 2) g_bar[t] = 0;
    for (int p = t; p < NL * 256; p += 256) (&g_mean[0][0])[p] = 0.f;
    for (int p = t; p < NEL * NI; p += blockDim.x) {
        int j = p >> 5, m = p & 31;
        float dx = ep[j * 3 + 0] - nuc[m * 3 + 0];
        float dy = ep[j * 3 + 1] - nuc[m * 3 + 1];
        float dz = ep[j * 3 + 2] - nuc[m * 3 + 2];
        float r  = sqrtf(dx * dx + dy * dy + dz * dz);
        g_sh[0][j][m * 3 + 0] = dx;
        g_sh[0][j][m * 3 + 1] = dy;
        g_sh[0][j][m * 3 + 2] = dz;
        g_sh[0][j][3 * NI + m] = r;
        g_rN[j][m] = r;
    }
    __syncthreads();
    // layer-0 means
    if (t < 128) {
        float s = 0.f;
#pragma unroll
        for (int r = 0; r < NUP; r++) s += g_sh[0][r][t];
        g_mean[0][t] = s * (1.0f / 16);
    } else {
        int o = t - 128;
        float s = 0.f;
#pragma unroll
        for (int r = NUP; r < NEL; r++) s += g_sh[0][r][o];
        g_mean[0][128 + o] = s * (1.0f / 16);
    }
}

// ---------------------------------------------------------------------------
// Fused persistent kernel. 128 blocks = 32 clusters of 4 (electron n = b>>2,
// og = b&3 = cluster rank). Own-sh + dg rows computed before the chip barrier
// (DSMEM-local); means are PRE-SUMMED via red.add.f32 from the previous
// layer's tail, so the post-barrier chain is just: 8 loads -> matvec ->
// reduce -> tanh -> publish.
// ---------------------------------------------------------------------------
__global__ void __launch_bounds__(256, 1) __cluster_dims__(4, 1, 1) fused_kernel(
    const float* __restrict__ ep, const float* __restrict__ nuc,
    const float* __restrict__ v,
    const float* __restrict__ b,  const float* __restrict__ w,
    const float* __restrict__ c,  const float* __restrict__ fw,
    const float* __restrict__ fb, const float* __restrict__ pi,
    const float* __restrict__ sigma, const float* __restrict__ omega,
    float* __restrict__ out)
{
    __shared__ float sh_loc[2][H1];     // full sh[n], double-buffered by parity
    __shared__ float pd[2][4][4];       // dh partial sums per og-rank
    __shared__ float dg_s[8];
    __shared__ float part_s[8][33];
    __shared__ float A[16][17];
    __shared__ float fac[16];
    __shared__ int   pivs;
    __shared__ float dsh;

    const int t    = threadIdx.x;
    const int n    = blockIdx.x >> 2;
    const int og   = blockIdx.x & 3;
    const int c4   = t & 7;
    const int fs   = t >> 3;
    const int lane = t & 31, wrp = t >> 5;
    const int dj   = og * 8 + t;        // this block's dh pair column (t<8)

    const uint32_t shloc_s = (uint32_t)__cvta_generic_to_shared(&sh_loc[0][0]);
    const uint32_t pd_s    = (uint32_t)__cvta_generic_to_shared(&pd[0][0][0]);

    // ---------------- prologue: local sh^0, dh^0 + partials ----------------
    if (t < H1) {
        float val;
        if (t < 96) {
            int m = t / 3, cp = t % 3;
            val = ep[n * 3 + cp] - nuc[m * 3 + cp];
        } else {
            int m = t - 96;
            float dx = ep[n * 3 + 0] - nuc[m * 3 + 0];
            float dy = ep[n * 3 + 1] - nuc[m * 3 + 1];
            float dz = ep[n * 3 + 2] - nuc[m * 3 + 2];
            val = sqrtf(dx * dx + dy * dy + dz * dz);
        }
        sh_loc[0][t] = val;
    }
    float4 d4;
    if (t < 8) {
        float dx = ep[n * 3 + 0] - ep[dj * 3 + 0];
        float dy = ep[n * 3 + 1] - ep[dj * 3 + 1];
        float dz = ep[n * 3 + 2] - ep[dj * 3 + 2];
        d4 = make_float4(dx, dy, dz, sqrtf(dx * dx + dy * dy + dz * dz));
        float4 s = d4;
        s.x += __shfl_down_sync(0xffu, s.x, 4, 8);
        s.y += __shfl_down_sync(0xffu, s.y, 4, 8);
        s.z += __shfl_down_sync(0xffu, s.z, 4, 8);
        s.w += __shfl_down_sync(0xffu, s.w, 4, 8);
        s.x += __shfl_down_sync(0xffu, s.x, 2, 8);
        s.y += __shfl_down_sync(0xffu, s.y, 2, 8);
        s.z += __shfl_down_sync(0xffu, s.z, 2, 8);
        s.w += __shfl_down_sync(0xffu, s.w, 2, 8);
        s.x += __shfl_down_sync(0xffu, s.x, 1, 8);
        s.y += __shfl_down_sync(0xffu, s.y, 1, 8);
        s.z += __shfl_down_sync(0xffu, s.z, 1, 8);
        s.w += __shfl_down_sync(0xffu, s.w, 1, 8);
        if (t == 0) {
            uint32_t base = pd_s + (0 * 4 + og) * 16;   // pd[0][og][0..3]
            for (int rk = 0; rk < 4; rk++) {
                uint32_t ra = mapa_addr(base, rk);
                st_dsm(ra + 0,  s.x);
                st_dsm(ra + 4,  s.y);
                st_dsm(ra + 8,  s.z);
                st_dsm(ra + 12, s.w);
            }
        }
    }
    cluster_arrive();

    float4 wr[13];
    float4 dw0, dw1, dw2, dw3, dc4;

#pragma unroll 1
    for (int l = 0; l < NL; l++) {
        const int p   = l & 1;          // sh_loc / pd buffer parity
        const int cur = l & 1, nxt = cur ^ 1;

        // ---- prefetch weights for this layer (fly during waits) ----
        {
            const float* vp = v + (((size_t)l * NEL + n) * FLEN) * H1 + og * 32 + c4 * 4;
#pragma unroll
            for (int i = 0; i < 12; i++)
                wr[i] = *reinterpret_cast<const float4*>(vp + (size_t)(fs + 32 * i) * H1);
            if (fs < 8)
                wr[12] = *reinterpret_cast<const float4*>(vp + (size_t)(fs + 384) * H1);
        }
        float bias_r = 0.f;
        if (t < 32) bias_r = b[((size_t)l * NEL + n) * H1 + og * 32 + t];
        const bool do_d = (t < 8) && (l < NL - 1);
        if (do_d) {
            const float* wp = w + ((size_t)(l * NEL + n) * NEL + dj) * 16;
            dw0 = *reinterpret_cast<const float4*>(wp);
            dw1 = *reinterpret_cast<const float4*>(wp + 4);
            dw2 = *reinterpret_cast<const float4*>(wp + 8);
            dw3 = *reinterpret_cast<const float4*>(wp + 12);
            dc4 = *reinterpret_cast<const float4*>(
                c + ((size_t)(l * NEL + n) * NEL + dj) * 4);
        }

        // ---- cluster-local data ready (sh_loc[p], pd[p]) ----
        cluster_wait();
        if (t < 8) {
            int d = t & 3;
            float a = (t < 4) ? (pd[p][0][d] + pd[p][1][d])
                              : (pd[p][2][d] + pd[p][3][d]);
            dg_s[t] = a * (1.0f / 16);
        }
        __syncthreads();

        // ---- LOCAL matvec part (rows 0..127 = own sh, 384..391 = dg) ----
        float4 acc = make_float4(0.f, 0.f, 0.f, 0.f);
#pragma unroll
        for (int i = 0; i < 4; i++) {
            float s = sh_loc[p][fs + 32 * i];
            acc.x += s * wr[i].x; acc.y += s * wr[i].y;
            acc.z += s * wr[i].z; acc.w += s * wr[i].w;
        }
        if (fs < 8) {
            float s = dg_s[fs];
            acc.x += s * wr[12].x; acc.y += s * wr[12].y;
            acc.z += s * wr[12].z; acc.w += s * wr[12].w;
        }

        // ---- dh update (local, register-resident) overlaps the chip wait ----
        float4 od;
        if (do_d) {
            float o0 = d4.x * dw0.x + d4.y * dw1.x + d4.z * dw2.x + d4.w * dw3.x;
            float o1 = d4.x * dw0.y + d4.y * dw1.y + d4.z * dw2.y + d4.w * dw3.y;
            float o2 = d4.x * dw0.z + d4.y * dw1.z + d4.z * dw2.z + d4.w * dw3.z;
            float o3 = d4.x * dw0.w + d4.y * dw1.w + d4.z * dw2.w + d4.w * dw3.w;
            od.x = tanhf(o0 + dc4.x) + d4.x;
            od.y = tanhf(o1 + dc4.y) + d4.y;
            od.z = tanhf(o2 + dc4.z) + d4.z;
            od.w = tanhf(o3 + dc4.w) + d4.w;
        }

        // ---- chip barrier: previous layer's mean sums visible ----
        if (l > 0) bar_wait(l - 1, GRID);

        // ---- MEAN matvec part (rows 128..383): pre-summed means, 8 loads ----
        {
            float m0 = __ldcg(&g_mean[l][fs]);
            float m1 = __ldcg(&g_mean[l][fs + 32]);
            float m2 = __ldcg(&g_mean[l][fs + 64]);
            float m3 = __ldcg(&g_mean[l][fs + 96]);
            float m4 = __ldcg(&g_mean[l][fs + 128]);
            float m5 = __ldcg(&g_mean[l][fs + 160]);
            float m6 = __ldcg(&g_mean[l][fs + 192]);
            float m7 = __ldcg(&g_mean[l][fs + 224]);
            acc.x += m0 * wr[4].x;  acc.y += m0 * wr[4].y;
            acc.z += m0 * wr[4].z;  acc.w += m0 * wr[4].w;
            acc.x += m1 * wr[5].x;  acc.y += m1 * wr[5].y;
            acc.z += m1 * wr[5].z;  acc.w += m1 * wr[5].w;
            acc.x += m2 * wr[6].x;  acc.y += m2 * wr[6].y;
            acc.z += m2 * wr[6].z;  acc.w += m2 * wr[6].w;
            acc.x += m3 * wr[7].x;  acc.y += m3 * wr[7].y;
            acc.z += m3 * wr[7].z;  acc.w += m3 * wr[7].w;
            acc.x += m4 * wr[8].x;  acc.y += m4 * wr[8].y;
            acc.z += m4 * wr[8].z;  acc.w += m4 * wr[8].w;
            acc.x += m5 * wr[9].x;  acc.y += m5 * wr[9].y;
            acc.z += m5 * wr[9].z;  acc.w += m5 * wr[9].w;
            acc.x += m6 * wr[10].x; acc.y += m6 * wr[10].y;
            acc.z += m6 * wr[10].z; acc.w += m6 * wr[10].w;
            acc.x += m7 * wr[11].x; acc.y += m7 * wr[11].y;
            acc.z += m7 * wr[11].z; acc.w += m7 * wr[11].w;
        }

        // ---- reduce ----
#pragma unroll
        for (int off = 16; off >= 8; off >>= 1) {
            acc.x += __shfl_down_sync(0xffffffffu, acc.x, off);
            acc.y += __shfl_down_sync(0xffffffffu, acc.y, off);
            acc.z += __shfl_down_sync(0xffffffffu, acc.z, off);
            acc.w += __shfl_down_sync(0xffffffffu, acc.w, off);
        }
        if (lane < 8) {
            part_s[wrp][lane * 4 + 0] = acc.x;
            part_s[wrp][lane * 4 + 1] = acc.y;
            part_s[wrp][lane * 4 + 2] = acc.z;
            part_s[wrp][lane * 4 + 3] = acc.w;
        }
        __syncthreads();

        // ---- tail: 32 threads, one output column each ----
        if (t < 32) {
            float a = part_s[0][t];
#pragma unroll
            for (int ww = 1; ww < 8; ww++) a += part_s[ww][t];
            int o = og * 32 + t;
            float val = tanhf(a + bias_r) + sh_loc[p][o];
            __stcg(&g_sh[nxt][n][o], val);                       // for phi
            if (l < NL - 1) {
                // accumulate next layer's mean (pre-scaled)
                red_add_f32(&g_mean[l + 1][(n < NUP ? 0 : 128) + o],
                            val * (1.0f / 16));
                // DSMEM broadcast of own sh slice to the cluster
                uint32_t base = shloc_s + ((p ^ 1) * H1 + o) * 4;
#pragma unroll
                for (int rk = 0; rk < 4; rk++)
                    st_dsm(mapa_addr(base, rk), val);
            }
        }

        // ---- dh partials for next layer ----
        if (do_d) {
            d4 = od;
            float4 s = d4;
            s.x += __shfl_down_sync(0xffu, s.x, 4, 8);
            s.y += __shfl_down_sync(0xffu, s.y, 4, 8);
            s.z += __shfl_down_sync(0xffu, s.z, 4, 8);
            s.w += __shfl_down_sync(0xffu, s.w, 4, 8);
            s.x += __shfl_down_sync(0xffu, s.x, 2, 8);
            s.y += __shfl_down_sync(0xffu, s.y, 2, 8);
            s.z += __shfl_down_sync(0xffu, s.z, 2, 8);
            s.w += __shfl_down_sync(0xffu, s.w, 2, 8);
            s.x += __shfl_down_sync(0xffu, s.x, 1, 8);
            s.y += __shfl_down_sync(0xffu, s.y, 1, 8);
            s.z += __shfl_down_sync(0xffu, s.z, 1, 8);
            s.w += __shfl_down_sync(0xffu, s.w, 1, 8);
            if (t == 0) {
                uint32_t base = pd_s + (((p ^ 1) * 4 + og) * 4) * 4;
                for (int rk = 0; rk < 4; rk++) {
                    uint32_t ra = mapa_addr(base, rk);
                    st_dsm(ra + 0,  s.x);
                    st_dsm(ra + 4,  s.y);
                    st_dsm(ra + 8,  s.z);
                    st_dsm(ra + 12, s.w);
                }
            }
        }
        if (l < NL - 1) cluster_arrive();
        bar_arrive(l);
    }

    // ================= phi (diagonal 16x16 blocks only) =================
    bar_wait(NL - 1, GRID);
    {
        const int k    = blockIdx.x >> 3;
        const int i    = (blockIdx.x & 7) * 4 + (t >> 6);
        const int spin = i >> 4;
        const int tl   = t & 63;
        const int jl   = tl >> 2, s = tl & 3;
        const int j    = spin * 16 + jl;
        const float* fwp = fw + (size_t)(k * NEL + i) * H1;
        float dot = 0.f;
#pragma unroll
        for (int q = 0; q < 32; q++)
            dot += fwp[s + 4 * q] * __ldcg(&g_sh[0][j][s + 4 * q]);
        const float* pip = pi    + (size_t)(k * NEL + i) * NI;
        const float* sgp = sigma + (size_t)(k * NEL + i) * NI;
        float env = 0.f;
#pragma unroll
        for (int q = 0; q < 8; q++) {
            int m = s * 8 + q;
            env += pip[m] * __expf(-fabsf(sgp[m]) * g_rN[j][m]);
        }
        dot += __shfl_down_sync(0xffffffffu, dot, 2, 4);
        dot += __shfl_down_sync(0xffffffffu, dot, 1, 4);
        env += __shfl_down_sync(0xffffffffu, env, 2, 4);
        env += __shfl_down_sync(0xffffffffu, env, 1, 4);
        if (s == 0)
            __stcg(&g_phi[k][spin][i & 15][jl], (dot + fb[k * NEL + i]) * env);
    }
    bar_arrive(NL);

    // ================= determinants (blocks 0..31) =================
    if (blockIdx.x < 32) {
        bar_wait(NL, GRID);
        const int k = blockIdx.x >> 1, spin = blockIdx.x & 1;
        const int r = t >> 4, cc = t & 15;
        A[r][cc] = __ldcg(&g_phi[k][spin][r][cc]);
        if (t == 0) dsh = 1.0f;
        __syncthreads();
        for (int pp = 0; pp < 16; pp++) {
            if (t == 0) {
                int best = pp;
                float bv = fabsf(A[pp][pp]);
                for (int rr = pp + 1; rr < 16; rr++) {
                    float v2 = fabsf(A[rr][pp]);
                    if (v2 > bv) { bv = v2; best = rr; }
                }
                pivs = best;
                if (best != pp) dsh = -dsh;
            }
            __syncthreads();
            int piv = pivs;
            if (piv != pp && t < 16) {
                float tmp = A[pp][t]; A[pp][t] = A[piv][t]; A[piv][t] = tmp;
            }
            __syncthreads();
            if (t < 16 && t > pp) fac[t] = A[t][pp] / A[pp][pp];
            if (t == 0) dsh *= A[pp][pp];
            __syncthreads();
            if (r > pp && cc > pp) A[r][cc] -= fac[r] * A[pp][cc];
            __syncthreads();
        }
        if (t == 0) __stcg(&g_det[k][spin], dsh);
        bar_arrive(NL + 1);
    }

    // ================= final reduction (block 0) =================
    if (blockIdx.x == 0) {
        bar_wait(NL + 1, 32);
        if (t < 32) {
            float vv = (t < NK) ? omega[t] * __ldcg(&g_det[t][0]) * __ldcg(&g_det[t][1])
                                : 0.0f;
#pragma unroll
            for (int off = 16; off; off >>= 1)
                vv += __shfl_down_sync(0xffffffffu, vv, off);
            if (t == 0) out[0] = vv;
        }
    }
}

extern "C" void kernel_launch(void* const* d_in, const int* in_sizes, int n_in,
                              void* d_out, int out_size) {
    const float* ep    = (const float*)d_in[0];
    const float* nuc   = (const float*)d_in[1];
    const float* v     = (const float*)d_in[2];
    const float* b     = (const float*)d_in[3];
    const float* w     = (const float*)d_in[4];
    const float* c     = (const float*)d_in[5];
    const float* fw    = (const float*)d_in[6];
    const float* fb    = (const float*)d_in[7];
    const float* pi    = (const float*)d_in[8];
    const float* sigma = (const float*)d_in[9];
    const float* omega = (const float*)d_in[10];

    pre_kernel<<<1, 256>>>(ep, nuc);
    fused_kernel<<<GRID, 256>>>(ep, nuc, v, b, w, c, fw, fb, pi, sigma, omega,
                                (float*)d_out);
}